// round 15
// baseline (speedup 1.0000x reference)
#include <cuda_runtime.h>
#include <cuda_bf16.h>
#include <cuda_fp16.h>
#include <math.h>
#include <stdint.h>

#define N_NODES_MAX 100000
#define NEG_SLOPE 0.2f
#define LOG2E 1.4426950408889634f

// ---------------- scratch (device globals: alloc-free) ----------------
__device__ float    g_el[N_NODES_MAX * 4];    // pre-scaled by LOG2E
__device__ float    g_er[N_NODES_MAX * 4];    // pre-scaled by LOG2E
__device__ int      g_offs[N_NODES_MAX + 1];
__device__ uint32_t g_fth[N_NODES_MAX * 64];  // fp16 ft rows: 64 uint32 = 128 half
__device__ uint4    g_Bh4[2048];              // fp16 B[n][k] image (128x128 = 32KB)

__device__ __forceinline__ uint32_t smem_u32(const void* p) {
    uint32_t a;
    asm("{ .reg .u64 t; cvta.to.shared.u64 t, %1; cvt.u32.u64 %0, t; }" : "=r"(a) : "l"(p));
    return a;
}

#define LDM4(r, addr) \
    asm volatile("ldmatrix.sync.aligned.m8n8.x4.shared.b16 {%0,%1,%2,%3}, [%4];" \
        : "=r"((r)[0]), "=r"((r)[1]), "=r"((r)[2]), "=r"((r)[3]) : "r"(addr))

#define MMA_F16(c, a, b) \
    asm volatile("mma.sync.aligned.m16n8k16.row.col.f32.f16.f16.f32 " \
        "{%0,%1,%2,%3}, {%4,%5,%6,%7}, {%8,%9}, {%0,%1,%2,%3};" \
        : "+f"((c)[0]), "+f"((c)[1]), "+f"((c)[2]), "+f"((c)[3]) \
        : "r"((a)[0]), "r"((a)[1]), "r"((a)[2]), "r"((a)[3]), "r"((b)[0]), "r"((b)[1]))

// smem: padded rows of 136 half = 272 B (17x16B -> conflict-free ldmatrix)
#define ROWB 272
#define SA    0
#define SB    (SA + 128 * ROWB)
#define SM_TOTAL (SB + 128 * ROWB)   // 69632 B -> 2 CTAs/SM

// ------- 0) prep: W -> fp16 B image (blocks 0..63) + offsets scatter (64..) ----
// dst sorted. Each offsets-thread owns 16 edges via four int4 loads; boundary
// compares fill offs[n]=i for gaps. offs[n] = first i with dst[i] >= n.
__global__ void prep_kernel(const float* __restrict__ W,
                            const int* __restrict__ dst, int N, int E) {
    int b = blockIdx.x;
    if (b < 64) {
        int idx = b * 256 + threadIdx.x;        // 0..16383
        int k = idx >> 7, n = idx & 127;
        ((__half*)g_Bh4)[n * 128 + k] = __float2half_rn(W[idx]);
        return;
    }
    int base = ((b - 64) * 256 + threadIdx.x) * 16;   // first edge of this group
    if (base >= E) return;

    int d[16];
    int cnt;
    if (base + 16 <= E && ((base & 3) == 0)) {
#pragma unroll
        for (int v = 0; v < 4; v++) {
            int4 t = *(const int4*)(dst + base + v * 4);
            d[v * 4 + 0] = t.x; d[v * 4 + 1] = t.y; d[v * 4 + 2] = t.z; d[v * 4 + 3] = t.w;
        }
        cnt = 16;
    } else {
        cnt = E - base; if (cnt > 16) cnt = 16;
        for (int k = 0; k < cnt; k++) d[k] = __ldg(dst + base + k);
        for (int k = cnt; k < 16; k++) d[k] = 0;
    }
    int prev = (base == 0) ? -1 : __ldg(dst + base - 1);
#pragma unroll
    for (int k = 0; k < 16; k++) {
        if (k < cnt) {
            for (int n = prev + 1; n <= d[k]; n++) g_offs[n] = base + k;
            prev = d[k];
        }
    }
    if (base + cnt >= E) {                        // this thread owns the last edge
        for (int n = prev + 1; n <= N; n++) g_offs[n] = E;
    }
}

// ---------------- 1) mma.sync single-term fp16 GEMM + fused ft / el / er -------
__global__ __launch_bounds__(256, 2) void gemm_mma_kernel(const float* __restrict__ A,
                                                          const float* __restrict__ attn_l,
                                                          const float* __restrict__ attn_r,
                                                          int M) {
    extern __shared__ char smem[];
    const uint32_t sb = smem_u32(smem);
    const int tid = threadIdx.x, wid = tid >> 5, lane = tid & 31;
    const int bm = blockIdx.x * 128;
    const bool full = (bm + 128 <= M);

    if (full) {
        // fast path: batch loads for MLP (8 B-LDGs + 8 A-LDGs in flight), no predicates
        uint4 bv[8];
#pragma unroll
        for (int i = 0; i < 8; i++) bv[i] = g_Bh4[tid + i * 256];
        float4 av4[8];
#pragma unroll
        for (int it = 0; it < 8; it++) {
            int idx = tid + it * 256;
            av4[it] = *(const float4*)(A + (size_t)(bm + (idx >> 5)) * 128 + (idx & 31) * 4);
        }
#pragma unroll
        for (int i = 0; i < 8; i++) {
            int t = tid + i * 256;
            *(uint4*)(smem + SB + (t >> 4) * ROWB + (t & 15) * 16) = bv[i];
        }
#pragma unroll
        for (int it = 0; it < 8; it++) {
            int idx = tid + it * 256;
            __half2 hA = __floats2half2_rn(av4[it].x, av4[it].y);
            __half2 hB = __floats2half2_rn(av4[it].z, av4[it].w);
            *(uint2*)(smem + SA + (idx >> 5) * ROWB + (idx & 31) * 8) =
                make_uint2(*(uint32_t*)&hA, *(uint32_t*)&hB);
        }
#pragma unroll
        for (int it = 8; it < 16; it++) {
            int idx = tid + it * 256;
            float4 v = *(const float4*)(A + (size_t)(bm + (idx >> 5)) * 128 + (idx & 31) * 4);
            __half2 hA = __floats2half2_rn(v.x, v.y);
            __half2 hB = __floats2half2_rn(v.z, v.w);
            *(uint2*)(smem + SA + (idx >> 5) * ROWB + (idx & 31) * 8) =
                make_uint2(*(uint32_t*)&hA, *(uint32_t*)&hB);
        }
    } else {
        for (int i = tid; i < 2048; i += 256) {
            int row = i >> 4, c = i & 15;
            *(uint4*)(smem + SB + row * ROWB + c * 16) = g_Bh4[i];
        }
#pragma unroll 4
        for (int it = 0; it < 16; it++) {
            int idx = tid + it * 256;
            int row = idx >> 5, c4 = (idx & 31) * 4;
            float4 v = make_float4(0.f, 0.f, 0.f, 0.f);
            if (bm + row < M) v = *(const float4*)(A + (size_t)(bm + row) * 128 + c4);
            __half2 hA = __floats2half2_rn(v.x, v.y);
            __half2 hB = __floats2half2_rn(v.z, v.w);
            *(uint2*)(smem + SA + row * ROWB + c4 * 2) = make_uint2(*(uint32_t*)&hA, *(uint32_t*)&hB);
        }
    }
    __syncthreads();

    const int wm = wid & 3, wn = wid >> 2;
    const int m0 = wm * 32, n0 = wn * 64;

    float acc[2][8][4];
#pragma unroll
    for (int i = 0; i < 2; i++)
#pragma unroll
        for (int j = 0; j < 8; j++)
#pragma unroll
            for (int q = 0; q < 4; q++) acc[i][j][q] = 0.f;

    // ldmatrix per-lane base addresses
    const uint32_t a_row = m0 + (lane & 15);
    const uint32_t a_off = a_row * ROWB + ((lane >> 4) << 4);
    const uint32_t b_row = n0 + (lane & 7) + ((lane >> 4) << 3);
    const uint32_t b_off = b_row * ROWB + (((lane >> 3) & 1) << 4);
    const uint32_t a_b = sb + SA + a_off;
    const uint32_t b_b = sb + SB + b_off;

#pragma unroll
    for (int ks = 0; ks < 8; ks++) {
        const uint32_t k0b = ks * 32;   // 16 cols * 2B
        uint32_t av[2][4], bh[8][2];
        LDM4(av[0], a_b + k0b);
        LDM4(av[1], a_b + 16 * ROWB + k0b);
#pragma unroll
        for (int jj = 0; jj < 4; jj++) {
            uint32_t r[4];
            LDM4(r, b_b + jj * 16 * ROWB + k0b);
            bh[2 * jj][0] = r[0]; bh[2 * jj][1] = r[1];
            bh[2 * jj + 1][0] = r[2]; bh[2 * jj + 1][1] = r[3];
        }
#pragma unroll
        for (int im = 0; im < 2; im++)
#pragma unroll
            for (int jn = 0; jn < 8; jn++)
                MMA_F16(acc[im][jn], av[im], bh[jn]);
    }

    // epilogue: fp16 ft + exact el/er (quad owns full 32-col head dot)
    // attn vectors pre-scaled by LOG2E so agg can use bare ex2.
    float alv[16], arv[16];
#pragma unroll
    for (int j = 0; j < 8; j++) {
        int c0 = n0 + j * 8 + 2 * (lane & 3);
        alv[2 * j] = __ldg(attn_l + c0) * LOG2E; alv[2 * j + 1] = __ldg(attn_l + c0 + 1) * LOG2E;
        arv[2 * j] = __ldg(attn_r + c0) * LOG2E; arv[2 * j + 1] = __ldg(attn_r + c0 + 1) * LOG2E;
    }
    const int hA = n0 >> 5;            // heads hA, hA+1
#pragma unroll
    for (int im = 0; im < 2; im++) {
#pragma unroll
        for (int hf = 0; hf < 2; hf++) {
            int row = bm + m0 + im * 16 + (lane >> 2) + hf * 8;
            float sA = 0.f, sB = 0.f, rA = 0.f, rB = 0.f;
            uint32_t pk[8];
#pragma unroll
            for (int j = 0; j < 8; j++) {
                float v0 = acc[im][j][hf * 2], v1 = acc[im][j][hf * 2 + 1];
                __half2 hh = __floats2half2_rn(v0, v1);
                pk[j] = *(uint32_t*)&hh;
                if (j < 4) {
                    sA = fmaf(v0, alv[2 * j], fmaf(v1, alv[2 * j + 1], sA));
                    rA = fmaf(v0, arv[2 * j], fmaf(v1, arv[2 * j + 1], rA));
                } else {
                    sB = fmaf(v0, alv[2 * j], fmaf(v1, alv[2 * j + 1], sB));
                    rB = fmaf(v0, arv[2 * j], fmaf(v1, arv[2 * j + 1], rB));
                }
            }
            if (row < M) {
                uint32_t* dst = g_fth + (size_t)row * 64 + (n0 >> 1) + (lane & 3);
#pragma unroll
                for (int j = 0; j < 8; j++) dst[j * 4] = pk[j];
            }
            sA += __shfl_xor_sync(~0u, sA, 1); sA += __shfl_xor_sync(~0u, sA, 2);
            sB += __shfl_xor_sync(~0u, sB, 1); sB += __shfl_xor_sync(~0u, sB, 2);
            rA += __shfl_xor_sync(~0u, rA, 1); rA += __shfl_xor_sync(~0u, rA, 2);
            rB += __shfl_xor_sync(~0u, rB, 1); rB += __shfl_xor_sync(~0u, rB, 2);
            if ((lane & 3) == 0 && row < M) {
                g_el[row * 4 + hA]     = sA;
                g_el[row * 4 + hA + 1] = sB;
                g_er[row * 4 + hA]     = rA;
                g_er[row * 4 + hA + 1] = rB;
            }
        }
    }
}

// ---------------- 2) aggregation: 1 warp/node, half-warp per edge, FFMA2 -------
// unroll 4: four independent LDG chains in flight per warp.
__global__ __launch_bounds__(256) void agg_kernel(const int* __restrict__ src,
                                                  float* __restrict__ out, int N) {
    int gid  = blockIdx.x * blockDim.x + threadIdx.x;
    int node = gid >> 5;
    int lane = gid & 31;
    if (node >= N) return;

    const int half = lane >> 4;       // 0/1: which edge of the pair
    const int sl   = lane & 15;       // feature slice: halves [8*sl, 8*sl+8)
    const int h    = sl >> 2;         // head of this slice

    int s = g_offs[node];
    int e = g_offs[node + 1];
    float er_h = g_er[node * 4 + h];

    float psum = 0.f;
    unsigned long long acc[4];
#pragma unroll
    for (int q = 0; q < 4; q++) acc[q] = 0ull;

    const uint4* ft = (const uint4*)g_fth;   // 16 uint4 per row
#pragma unroll 4
    for (int i = s + half; i < e; i += 2) {
        int sn = __ldg(src + i);
        float sc = __ldg(&g_el[sn * 4 + h]) + er_h;   // already in log2 domain
        sc = fmaxf(sc, NEG_SLOPE * sc);               // leaky commutes with +scale
        float p;
        asm("ex2.approx.f32 %0, %1;" : "=f"(p) : "f"(sc));
        psum += p;
        unsigned long long pp;
        asm("mov.b64 %0, {%1, %1};" : "=l"(pp) : "r"(__float_as_uint(p)));
        uint4 v = __ldg(&ft[(size_t)sn * 16 + sl]);
        const __half2* hv = (const __half2*)&v;
#pragma unroll
        for (int q = 0; q < 4; q++) {
            float2 f = __half22float2(hv[q]);
            unsigned long long ff;
            asm("mov.b64 %0, {%1, %2};" : "=l"(ff)
                : "r"(__float_as_uint(f.x)), "r"(__float_as_uint(f.y)));
            asm("fma.rn.f32x2 %0, %1, %2, %0;" : "+l"(acc[q]) : "l"(pp), "l"(ff));
        }
    }

    // combine the two half-warps
    psum += __shfl_xor_sync(~0u, psum, 16);
    float a[8];
#pragma unroll
    for (int q = 0; q < 4; q++) {
        uint32_t lo, hi;
        asm("mov.b64 {%0, %1}, %2;" : "=r"(lo), "=r"(hi) : "l"(acc[q]));
        a[2 * q]     = __uint_as_float(lo);
        a[2 * q + 1] = __uint_as_float(hi);
    }
#pragma unroll
    for (int q = 0; q < 8; q++) a[q] += __shfl_xor_sync(~0u, a[q], 16);

    if (half == 0) {
        float inv = (psum > 0.f) ? (1.f / psum) : 0.f;
        float* dst = out + (size_t)node * 128 + sl * 8;
        *(float4*)dst       = make_float4(a[0] * inv, a[1] * inv, a[2] * inv, a[3] * inv);
        *(float4*)(dst + 4) = make_float4(a[4] * inv, a[5] * inv, a[6] * inv, a[7] * inv);
    }
}

// ---------------- launch ----------------
extern "C" void kernel_launch(void* const* d_in, const int* in_sizes, int n_in,
                              void* d_out, int out_size) {
    const float* feat   = (const float*)d_in[0];
    const int*   src    = (const int*)d_in[1];
    const int*   dst    = (const int*)d_in[2];
    const float* W      = (const float*)d_in[3];
    const float* attn_l = (const float*)d_in[4];
    const float* attn_r = (const float*)d_in[5];
    float* out = (float*)d_out;

    int M = in_sizes[0] / 128;   // nodes
    int E = in_sizes[1];         // edges

    cudaFuncSetAttribute(gemm_mma_kernel, cudaFuncAttributeMaxDynamicSharedMemorySize, SM_TOTAL);

    int groupBlocks = ((E + 15) / 16 + 255) / 256;
    prep_kernel<<<64 + groupBlocks, 256>>>(W, dst, M, E);
    gemm_mma_kernel<<<(M + 127) / 128, 256, SM_TOTAL>>>(feat, attn_l, attn_r, M);
    agg_kernel<<<((size_t)M * 32 + 255) / 256, 256>>>(src, out, M);
}

// round 16
// speedup vs baseline: 1.0928x; 1.0928x over previous
#include <cuda_runtime.h>
#include <cuda_bf16.h>
#include <cuda_fp16.h>
#include <math.h>
#include <stdint.h>

#define N_NODES_MAX 100000
#define NEG_SLOPE 0.2f
#define LOG2E 1.4426950408889634f

// ---------------- scratch (device globals: alloc-free) ----------------
__device__ float    g_el[N_NODES_MAX * 4];    // pre-scaled by LOG2E
__device__ float    g_er[N_NODES_MAX * 4];    // pre-scaled by LOG2E
__device__ int      g_offs[N_NODES_MAX + 1];
__device__ uint32_t g_fth[N_NODES_MAX * 64];  // fp16 ft rows: 64 uint32 = 128 half
__device__ uint4    g_Bh4[2048];              // fp16 B[n][k] image (128x128 = 32KB)

__device__ __forceinline__ uint32_t smem_u32(const void* p) {
    uint32_t a;
    asm("{ .reg .u64 t; cvta.to.shared.u64 t, %1; cvt.u32.u64 %0, t; }" : "=r"(a) : "l"(p));
    return a;
}

#define LDM4(r, addr) \
    asm volatile("ldmatrix.sync.aligned.m8n8.x4.shared.b16 {%0,%1,%2,%3}, [%4];" \
        : "=r"((r)[0]), "=r"((r)[1]), "=r"((r)[2]), "=r"((r)[3]) : "r"(addr))

#define MMA_F16(c, a, b) \
    asm volatile("mma.sync.aligned.m16n8k16.row.col.f32.f16.f16.f32 " \
        "{%0,%1,%2,%3}, {%4,%5,%6,%7}, {%8,%9}, {%0,%1,%2,%3};" \
        : "+f"((c)[0]), "+f"((c)[1]), "+f"((c)[2]), "+f"((c)[3]) \
        : "r"((a)[0]), "r"((a)[1]), "r"((a)[2]), "r"((a)[3]), "r"((b)[0]), "r"((b)[1]))

// smem: padded rows of 136 half = 272 B (17x16B -> conflict-free ldmatrix)
#define ROWB 272
#define SA    0
#define SB    (SA + 128 * ROWB)
#define SM_TOTAL (SB + 128 * ROWB)   // 69632 B -> 2 CTAs/SM

// ---------------- 0) prepB: W[k][n] -> fp16 B[n][k] image (tiny) ---------------
__global__ void prepB_kernel(const float* __restrict__ W) {
    int idx = blockIdx.x * blockDim.x + threadIdx.x;   // 0..16383
    int k = idx >> 7, n = idx & 127;
    ((__half*)g_Bh4)[n * 128 + k] = __float2half_rn(W[idx]);
}

// ---------------- 1) GEMM grid = gemm blocks ++ offsets-scatter blocks ---------
// Blocks >= gemmBlocks run the CSR-offsets scatter (8 edges/thread, round-13
// variant) and exit before touching smem -> scatter overlaps the GEMM waves.
__global__ __launch_bounds__(256, 2) void gemm_mma_kernel(const float* __restrict__ A,
                                                          const float* __restrict__ attn_l,
                                                          const float* __restrict__ attn_r,
                                                          const int* __restrict__ dstv,
                                                          int M, int E, int gemmBlocks) {
    // ---- offsets-scatter side grid ----
    if ((int)blockIdx.x >= gemmBlocks) {
        int base = (((int)blockIdx.x - gemmBlocks) * 256 + threadIdx.x) * 8;
        if (base >= E) return;
        int d[8];
        int cnt;
        if (base + 8 <= E && ((base & 3) == 0)) {
            int4 v0 = *(const int4*)(dstv + base);
            int4 v1 = *(const int4*)(dstv + base + 4);
            d[0] = v0.x; d[1] = v0.y; d[2] = v0.z; d[3] = v0.w;
            d[4] = v1.x; d[5] = v1.y; d[6] = v1.z; d[7] = v1.w;
            cnt = 8;
        } else {
            cnt = E - base; if (cnt > 8) cnt = 8;
            for (int k = 0; k < cnt; k++) d[k] = __ldg(dstv + base + k);
            for (int k = cnt; k < 8; k++) d[k] = 0;
        }
        int prev = (base == 0) ? -1 : __ldg(dstv + base - 1);
#pragma unroll
        for (int k = 0; k < 8; k++) {
            if (k < cnt) {
                for (int n = prev + 1; n <= d[k]; n++) g_offs[n] = base + k;
                prev = d[k];
            }
        }
        if (base + cnt >= E) {
            for (int n = prev + 1; n <= M; n++) g_offs[n] = E;
        }
        return;
    }

    // ---- GEMM blocks (identical to round-14 passing version) ----
    extern __shared__ char smem[];
    const uint32_t sb = smem_u32(smem);
    const int tid = threadIdx.x, wid = tid >> 5, lane = tid & 31;
    const int bm = blockIdx.x * 128;
    const bool full = (bm + 128 <= M);

    if (full) {
        uint4 bv[8];
#pragma unroll
        for (int i = 0; i < 8; i++) bv[i] = g_Bh4[tid + i * 256];
        float4 av4[8];
#pragma unroll
        for (int it = 0; it < 8; it++) {
            int idx = tid + it * 256;
            av4[it] = *(const float4*)(A + (size_t)(bm + (idx >> 5)) * 128 + (idx & 31) * 4);
        }
#pragma unroll
        for (int i = 0; i < 8; i++) {
            int t = tid + i * 256;
            *(uint4*)(smem + SB + (t >> 4) * ROWB + (t & 15) * 16) = bv[i];
        }
#pragma unroll
        for (int it = 0; it < 8; it++) {
            int idx = tid + it * 256;
            __half2 hA = __floats2half2_rn(av4[it].x, av4[it].y);
            __half2 hB = __floats2half2_rn(av4[it].z, av4[it].w);
            *(uint2*)(smem + SA + (idx >> 5) * ROWB + (idx & 31) * 8) =
                make_uint2(*(uint32_t*)&hA, *(uint32_t*)&hB);
        }
#pragma unroll
        for (int it = 8; it < 16; it++) {
            int idx = tid + it * 256;
            float4 v = *(const float4*)(A + (size_t)(bm + (idx >> 5)) * 128 + (idx & 31) * 4);
            __half2 hA = __floats2half2_rn(v.x, v.y);
            __half2 hB = __floats2half2_rn(v.z, v.w);
            *(uint2*)(smem + SA + (idx >> 5) * ROWB + (idx & 31) * 8) =
                make_uint2(*(uint32_t*)&hA, *(uint32_t*)&hB);
        }
    } else {
        for (int i = tid; i < 2048; i += 256) {
            int row = i >> 4, c = i & 15;
            *(uint4*)(smem + SB + row * ROWB + c * 16) = g_Bh4[i];
        }
#pragma unroll 4
        for (int it = 0; it < 16; it++) {
            int idx = tid + it * 256;
            int row = idx >> 5, c4 = (idx & 31) * 4;
            float4 v = make_float4(0.f, 0.f, 0.f, 0.f);
            if (bm + row < M) v = *(const float4*)(A + (size_t)(bm + row) * 128 + c4);
            __half2 hA = __floats2half2_rn(v.x, v.y);
            __half2 hB = __floats2half2_rn(v.z, v.w);
            *(uint2*)(smem + SA + row * ROWB + c4 * 2) = make_uint2(*(uint32_t*)&hA, *(uint32_t*)&hB);
        }
    }
    __syncthreads();

    const int wm = wid & 3, wn = wid >> 2;
    const int m0 = wm * 32, n0 = wn * 64;

    float acc[2][8][4];
#pragma unroll
    for (int i = 0; i < 2; i++)
#pragma unroll
        for (int j = 0; j < 8; j++)
#pragma unroll
            for (int q = 0; q < 4; q++) acc[i][j][q] = 0.f;

    const uint32_t a_row = m0 + (lane & 15);
    const uint32_t a_off = a_row * ROWB + ((lane >> 4) << 4);
    const uint32_t b_row = n0 + (lane & 7) + ((lane >> 4) << 3);
    const uint32_t b_off = b_row * ROWB + (((lane >> 3) & 1) << 4);
    const uint32_t a_b = sb + SA + a_off;
    const uint32_t b_b = sb + SB + b_off;

#pragma unroll
    for (int ks = 0; ks < 8; ks++) {
        const uint32_t k0b = ks * 32;   // 16 cols * 2B
        uint32_t av[2][4], bh[8][2];
        LDM4(av[0], a_b + k0b);
        LDM4(av[1], a_b + 16 * ROWB + k0b);
#pragma unroll
        for (int jj = 0; jj < 4; jj++) {
            uint32_t r[4];
            LDM4(r, b_b + jj * 16 * ROWB + k0b);
            bh[2 * jj][0] = r[0]; bh[2 * jj][1] = r[1];
            bh[2 * jj + 1][0] = r[2]; bh[2 * jj + 1][1] = r[3];
        }
#pragma unroll
        for (int im = 0; im < 2; im++)
#pragma unroll
            for (int jn = 0; jn < 8; jn++)
                MMA_F16(acc[im][jn], av[im], bh[jn]);
    }

    // epilogue: fp16 ft + exact el/er (quad owns full 32-col head dot)
    float alv[16], arv[16];
#pragma unroll
    for (int j = 0; j < 8; j++) {
        int c0 = n0 + j * 8 + 2 * (lane & 3);
        alv[2 * j] = __ldg(attn_l + c0) * LOG2E; alv[2 * j + 1] = __ldg(attn_l + c0 + 1) * LOG2E;
        arv[2 * j] = __ldg(attn_r + c0) * LOG2E; arv[2 * j + 1] = __ldg(attn_r + c0 + 1) * LOG2E;
    }
    const int hA = n0 >> 5;            // heads hA, hA+1
#pragma unroll
    for (int im = 0; im < 2; im++) {
#pragma unroll
        for (int hf = 0; hf < 2; hf++) {
            int row = bm + m0 + im * 16 + (lane >> 2) + hf * 8;
            float sA = 0.f, sB = 0.f, rA = 0.f, rB = 0.f;
            uint32_t pk[8];
#pragma unroll
            for (int j = 0; j < 8; j++) {
                float v0 = acc[im][j][hf * 2], v1 = acc[im][j][hf * 2 + 1];
                __half2 hh = __floats2half2_rn(v0, v1);
                pk[j] = *(uint32_t*)&hh;
                if (j < 4) {
                    sA = fmaf(v0, alv[2 * j], fmaf(v1, alv[2 * j + 1], sA));
                    rA = fmaf(v0, arv[2 * j], fmaf(v1, arv[2 * j + 1], rA));
                } else {
                    sB = fmaf(v0, alv[2 * j], fmaf(v1, alv[2 * j + 1], sB));
                    rB = fmaf(v0, arv[2 * j], fmaf(v1, arv[2 * j + 1], rB));
                }
            }
            if (row < M) {
                uint32_t* dst = g_fth + (size_t)row * 64 + (n0 >> 1) + (lane & 3);
#pragma unroll
                for (int j = 0; j < 8; j++) dst[j * 4] = pk[j];
            }
            sA += __shfl_xor_sync(~0u, sA, 1); sA += __shfl_xor_sync(~0u, sA, 2);
            sB += __shfl_xor_sync(~0u, sB, 1); sB += __shfl_xor_sync(~0u, sB, 2);
            rA += __shfl_xor_sync(~0u, rA, 1); rA += __shfl_xor_sync(~0u, rA, 2);
            rB += __shfl_xor_sync(~0u, rB, 1); rB += __shfl_xor_sync(~0u, rB, 2);
            if ((lane & 3) == 0 && row < M) {
                g_el[row * 4 + hA]     = sA;
                g_el[row * 4 + hA + 1] = sB;
                g_er[row * 4 + hA]     = rA;
                g_er[row * 4 + hA + 1] = rB;
            }
        }
    }
}

// ---------------- 2) aggregation: 1 warp/node, half-warp per edge, FFMA2 -------
// (identical to round-10..14 passing version, unroll 2)
__global__ __launch_bounds__(256) void agg_kernel(const int* __restrict__ src,
                                                  float* __restrict__ out, int N) {
    int gid  = blockIdx.x * blockDim.x + threadIdx.x;
    int node = gid >> 5;
    int lane = gid & 31;
    if (node >= N) return;

    const int half = lane >> 4;       // 0/1: which edge of the pair
    const int sl   = lane & 15;       // feature slice: halves [8*sl, 8*sl+8)
    const int h    = sl >> 2;         // head of this slice

    int s = g_offs[node];
    int e = g_offs[node + 1];
    float er_h = g_er[node * 4 + h];

    float psum = 0.f;
    unsigned long long acc[4];
#pragma unroll
    for (int q = 0; q < 4; q++) acc[q] = 0ull;

    const uint4* ft = (const uint4*)g_fth;   // 16 uint4 per row
#pragma unroll 2
    for (int i = s + half; i < e; i += 2) {
        int sn = __ldg(src + i);
        float sc = __ldg(&g_el[sn * 4 + h]) + er_h;   // already in log2 domain
        sc = fmaxf(sc, NEG_SLOPE * sc);               // leaky commutes with +scale
        float p;
        asm("ex2.approx.f32 %0, %1;" : "=f"(p) : "f"(sc));
        psum += p;
        unsigned long long pp;
        asm("mov.b64 %0, {%1, %1};" : "=l"(pp) : "r"(__float_as_uint(p)));
        uint4 v = __ldg(&ft[(size_t)sn * 16 + sl]);
        const __half2* hv = (const __half2*)&v;
#pragma unroll
        for (int q = 0; q < 4; q++) {
            float2 f = __half22float2(hv[q]);
            unsigned long long ff;
            asm("mov.b64 %0, {%1, %2};" : "=l"(ff)
                : "r"(__float_as_uint(f.x)), "r"(__float_as_uint(f.y)));
            asm("fma.rn.f32x2 %0, %1, %2, %0;" : "+l"(acc[q]) : "l"(pp), "l"(ff));
        }
    }

    // combine the two half-warps
    psum += __shfl_xor_sync(~0u, psum, 16);
    float a[8];
#pragma unroll
    for (int q = 0; q < 4; q++) {
        uint32_t lo, hi;
        asm("mov.b64 {%0, %1}, %2;" : "=r"(lo), "=r"(hi) : "l"(acc[q]));
        a[2 * q]     = __uint_as_float(lo);
        a[2 * q + 1] = __uint_as_float(hi);
    }
#pragma unroll
    for (int q = 0; q < 8; q++) a[q] += __shfl_xor_sync(~0u, a[q], 16);

    if (half == 0) {
        float inv = (psum > 0.f) ? (1.f / psum) : 0.f;
        float* dst = out + (size_t)node * 128 + sl * 8;
        *(float4*)dst       = make_float4(a[0] * inv, a[1] * inv, a[2] * inv, a[3] * inv);
        *(float4*)(dst + 4) = make_float4(a[4] * inv, a[5] * inv, a[6] * inv, a[7] * inv);
    }
}

// ---------------- launch ----------------
extern "C" void kernel_launch(void* const* d_in, const int* in_sizes, int n_in,
                              void* d_out, int out_size) {
    const float* feat   = (const float*)d_in[0];
    const int*   src    = (const int*)d_in[1];
    const int*   dst    = (const int*)d_in[2];
    const float* W      = (const float*)d_in[3];
    const float* attn_l = (const float*)d_in[4];
    const float* attn_r = (const float*)d_in[5];
    float* out = (float*)d_out;

    int M = in_sizes[0] / 128;   // nodes
    int E = in_sizes[1];         // edges

    cudaFuncSetAttribute(gemm_mma_kernel, cudaFuncAttributeMaxDynamicSharedMemorySize, SM_TOTAL);

    int gemmBlocks = (M + 127) / 128;
    int offsBlocks = ((E + 7) / 8 + 255) / 256;

    prepB_kernel<<<64, 256>>>(W);
    gemm_mma_kernel<<<gemmBlocks + offsBlocks, 256, SM_TOTAL>>>(
        feat, attn_l, attn_r, dst, M, E, gemmBlocks);
    agg_kernel<<<((size_t)M * 32 + 255) / 256, 256>>>(src, out, M);
}